// round 11
// baseline (speedup 1.0000x reference)
#include <cuda_runtime.h>
#include <cuda_fp16.h>
#include <cstdint>

#define VOCAB 100000
#define EMBED 64
#define NPOS  51200          // B*S = 1024*50
#define KIDS  20

// W transposed + converted to fp16: [VOCAB, EMBED] = 12.8 MB, L2-resident.
// One row = 64 halves = 128 B = exactly one cache line.
__device__ __align__(16) __half g_WTh[(size_t)VOCAB * EMBED];

// ---------------------------------------------------------------------------
// Kernel 1: transpose + convert  W[64, 100000] f32  ->  g_WTh[100000, 64] f16
// Tile: 32 (V) x 64 (E, full). Grid = 100000/32 = 3125 blocks of 256 threads.
// (Measured at DRAM floor ~4.8us; unchanged from R9.)
// ---------------------------------------------------------------------------
__global__ __launch_bounds__(256) void transpose_W_kernel(const float* __restrict__ W) {
    __shared__ float tile[64][33];
    const int tid = threadIdx.x;
    const int v0  = blockIdx.x * 32;

    #pragma unroll
    for (int i = 0; i < 2; ++i) {
        int j  = tid + i * 256;
        int e  = j >> 3;
        int vq = (j & 7) * 4;
        float4 val = *reinterpret_cast<const float4*>(W + (size_t)e * VOCAB + v0 + vq);
        tile[e][vq + 0] = val.x;
        tile[e][vq + 1] = val.y;
        tile[e][vq + 2] = val.z;
        tile[e][vq + 3] = val.w;
    }
    __syncthreads();

    {
        int v  = tid >> 3;
        int e8 = (tid & 7) * 8;
        __half2 h[4];
        #pragma unroll
        for (int i = 0; i < 4; ++i) {
            h[i] = __floats2half2_rn(tile[e8 + 2 * i][v], tile[e8 + 2 * i + 1][v]);
        }
        *reinterpret_cast<uint4*>(g_WTh + (size_t)(v0 + v) * EMBED + e8) =
            *reinterpret_cast<uint4*>(h);
    }
}

// ---------------------------------------------------------------------------
// Kernel 2: embedding-bag gather. ONE WARP PER POSITION. Lane l reads the
// half2 at byte offset 4*l of each 128B row -> every warp-LDG is a single
// cache line with zero address divergence (1 wavefront, no replays).
// 20 independent LDG.32 per lane (ids pre-staged in smem). fp32 accumulate.
// 8 positions per 256-thread block.
// ---------------------------------------------------------------------------
__global__ __launch_bounds__(256) void gather_sum_kernel(
    const int*   __restrict__ ids,    // [NPOS, KIDS]
    const float* __restrict__ bias,   // [EMBED]
    float*       __restrict__ out)    // [NPOS, EMBED]
{
    __shared__ int sids[8 * KIDS];    // 160 ids for this block's 8 positions

    const int tid  = threadIdx.x;
    const int pos0 = blockIdx.x * 8;

    // Coalesced cooperative id load (160 ints = 640B).
    if (tid < 8 * KIDS)
        sids[tid] = ids[(size_t)pos0 * KIDS + tid];
    __syncthreads();

    const int warp = tid >> 5;        // local position 0..7
    const int lane = tid & 31;        // owns embed elems [2*lane, 2*lane+1]
    const int* myids = sids + warp * KIDS;

    // Pre-read all 20 ids (independent broadcast LDS) so ptxas can
    // front-batch the 20 independent LDG.32s.
    int kid[KIDS];
    #pragma unroll
    for (int k = 0; k < KIDS; ++k) kid[k] = myids[k];

    // Load all 20 half2 values (20 independent single-line warp loads).
    __half2 w[KIDS];
    const __half* wt = g_WTh + (size_t)lane * 2;
    #pragma unroll
    for (int k = 0; k < KIDS; ++k)
        w[k] = *reinterpret_cast<const __half2*>(wt + (size_t)kid[k] * EMBED);

    // fp32 accumulation, two independent chains for ILP.
    float2 accA = make_float2(0.f, 0.f);
    float2 accB = make_float2(0.f, 0.f);
    #pragma unroll
    for (int k = 0; k < KIDS; k += 2) {
        float2 f0 = __half22float2(w[k]);
        float2 f1 = __half22float2(w[k + 1]);
        accA.x += f0.x; accA.y += f0.y;
        accB.x += f1.x; accB.y += f1.y;
    }
    accA.x += accB.x;
    accA.y += accB.y;

    const float2 bb = __ldg(reinterpret_cast<const float2*>(bias + lane * 2));
    accA.x += bb.x;
    accA.y += bb.y;

    // Warp store: 32 lanes x 8B = 256B contiguous.
    *reinterpret_cast<float2*>(out + (size_t)(pos0 + warp) * EMBED + lane * 2) = accA;
}

// ---------------------------------------------------------------------------
// inputs: 0 = content_input int32 [B,S,K], 1 = W f32 [E,V], 2 = b f32 [E]
// output: f32 [B,S,E]
// ---------------------------------------------------------------------------
extern "C" void kernel_launch(void* const* d_in, const int* in_sizes, int n_in,
                              void* d_out, int out_size) {
    const int*   ids  = (const int*)d_in[0];
    const float* W    = (const float*)d_in[1];
    const float* bias = (const float*)d_in[2];
    float*       out  = (float*)d_out;

    transpose_W_kernel<<<VOCAB / 32, 256>>>(W);           // 3125 blocks
    gather_sum_kernel<<<NPOS / 8, 256>>>(ids, bias, out); // 6400 blocks
}

// round 12
// speedup vs baseline: 1.0860x; 1.0860x over previous
#include <cuda_runtime.h>
#include <cuda_fp16.h>
#include <cstdint>

#define VOCAB 100000
#define EMBED 64
#define NPOS  51200          // B*S = 1024*50
#define KIDS  20

// W transposed + converted to fp16: [VOCAB, EMBED] = 12.8 MB, L2-resident.
// One row = 64 halves = 128 B = exactly one cache line.
__device__ __align__(16) __half g_WTh[(size_t)VOCAB * EMBED];

// L1-bypassing 16B load: no L1 line allocation (random gather, ~2% L1 hit
// rate -> allocation is pure overhead). L2 -> registers direct.
__device__ __forceinline__ uint4 ldg_na(const __half* p) {
    uint4 v;
    asm("ld.global.nc.L1::no_allocate.v4.b32 {%0,%1,%2,%3}, [%4];"
        : "=r"(v.x), "=r"(v.y), "=r"(v.z), "=r"(v.w)
        : "l"(p));
    return v;
}

// ---------------------------------------------------------------------------
// Kernel 1: transpose + convert  W[64, 100000] f32  ->  g_WTh[100000, 64] f16
// Tile: 32 (V) x 64 (E, full). Grid = 3125 blocks of 256. At DRAM floor.
// ---------------------------------------------------------------------------
__global__ __launch_bounds__(256) void transpose_W_kernel(const float* __restrict__ W) {
    __shared__ float tile[64][33];
    const int tid = threadIdx.x;
    const int v0  = blockIdx.x * 32;

    #pragma unroll
    for (int i = 0; i < 2; ++i) {
        int j  = tid + i * 256;
        int e  = j >> 3;
        int vq = (j & 7) * 4;
        float4 val = *reinterpret_cast<const float4*>(W + (size_t)e * VOCAB + v0 + vq);
        tile[e][vq + 0] = val.x;
        tile[e][vq + 1] = val.y;
        tile[e][vq + 2] = val.z;
        tile[e][vq + 3] = val.w;
    }
    __syncthreads();

    {
        int v  = tid >> 3;
        int e8 = (tid & 7) * 8;
        __half2 h[4];
        #pragma unroll
        for (int i = 0; i < 4; ++i) {
            h[i] = __floats2half2_rn(tile[e8 + 2 * i][v], tile[e8 + 2 * i + 1][v]);
        }
        *reinterpret_cast<uint4*>(g_WTh + (size_t)(v0 + v) * EMBED + e8) =
            *reinterpret_cast<uint4*>(h);
    }
}

// ---------------------------------------------------------------------------
// Kernel 2: embedding-bag gather (R9 shape + L1-bypass loads).
// 8 lanes per position, each lane one LDG.128 (8 halves) per id -> 8 lanes
// x 16B = full 128B row. 32 positions per 256-thread block. fp32 accum.
// ---------------------------------------------------------------------------
__global__ __launch_bounds__(256) void gather_sum_kernel(
    const int*   __restrict__ ids,    // [NPOS, KIDS]
    const float* __restrict__ bias,   // [EMBED]
    float*       __restrict__ out)    // [NPOS, EMBED]
{
    __shared__ int sids[32 * KIDS];   // 640 ids for this block's 32 positions

    const int tid  = threadIdx.x;
    const int pos0 = blockIdx.x * 32;

    // Coalesced cooperative id load (640 ints = 2560B).
    #pragma unroll
    for (int i = tid; i < 32 * KIDS; i += 256)
        sids[i] = ids[(size_t)pos0 * KIDS + i];
    __syncthreads();

    const int p   = tid >> 3;         // local position 0..31
    const int sub = tid & 7;          // owns embed elems [8*sub, 8*sub+8)
    const int* myids = sids + p * KIDS;
    const __half* wt = g_WTh + (size_t)sub * 8;

    float acc[8];
    #pragma unroll
    for (int i = 0; i < 8; ++i) acc[i] = 0.f;

    #pragma unroll
    for (int k = 0; k < KIDS; ++k) {
        uint4 raw = ldg_na(wt + (size_t)myids[k] * EMBED);
        const __half2* h = reinterpret_cast<const __half2*>(&raw);
        #pragma unroll
        for (int i = 0; i < 4; ++i) {
            float2 f = __half22float2(h[i]);
            acc[2 * i]     += f.x;
            acc[2 * i + 1] += f.y;
        }
    }

    // Bias (fp32, exact) + output write: 8 floats = two float4.
    const float4 b0 = __ldg(reinterpret_cast<const float4*>(bias + sub * 8));
    const float4 b1 = __ldg(reinterpret_cast<const float4*>(bias + sub * 8 + 4));

    float4 r0 = make_float4(acc[0] + b0.x, acc[1] + b0.y, acc[2] + b0.z, acc[3] + b0.w);
    float4 r1 = make_float4(acc[4] + b1.x, acc[5] + b1.y, acc[6] + b1.z, acc[7] + b1.w);

    float* op = out + (size_t)(pos0 + p) * EMBED + sub * 8;
    *reinterpret_cast<float4*>(op)     = r0;
    *reinterpret_cast<float4*>(op + 4) = r1;
}

// ---------------------------------------------------------------------------
// inputs: 0 = content_input int32 [B,S,K], 1 = W f32 [E,V], 2 = b f32 [E]
// output: f32 [B,S,E]
// ---------------------------------------------------------------------------
extern "C" void kernel_launch(void* const* d_in, const int* in_sizes, int n_in,
                              void* d_out, int out_size) {
    const int*   ids  = (const int*)d_in[0];
    const float* W    = (const float*)d_in[1];
    const float* bias = (const float*)d_in[2];
    float*       out  = (float*)d_out;

    transpose_W_kernel<<<VOCAB / 32, 256>>>(W);            // 3125 blocks
    gather_sum_kernel<<<NPOS / 32, 256>>>(ids, bias, out); // 1600 blocks
}

// round 13
// speedup vs baseline: 1.0992x; 1.0122x over previous
#include <cuda_runtime.h>
#include <cuda_fp16.h>
#include <cstdint>

#define VOCAB 100000
#define EMBED 64
#define NPOS  51200          // B*S = 1024*50
#define KIDS  20

// W transposed + converted to fp16: [VOCAB, EMBED] = 12.8 MB, L2-resident.
// One row = 64 halves = 128 B = exactly one cache line.
__device__ __align__(16) __half g_WTh[(size_t)VOCAB * EMBED];

// L1-bypassing 16B load: no L1 line allocation (random gather, ~2% L1 hit
// rate -> allocation is pure overhead). L2 -> registers direct.
__device__ __forceinline__ uint4 ldg_na(const __half* p) {
    uint4 v;
    asm("ld.global.nc.L1::no_allocate.v4.b32 {%0,%1,%2,%3}, [%4];"
        : "=r"(v.x), "=r"(v.y), "=r"(v.z), "=r"(v.w)
        : "l"(p));
    return v;
}

// ---------------------------------------------------------------------------
// Kernel 1: transpose + convert  W[64, 100000] f32  ->  g_WTh[100000, 64] f16
// Tile: 32 (V) x 64 (E, full). Grid = 3125 blocks of 256. At DRAM floor.
// ---------------------------------------------------------------------------
__global__ __launch_bounds__(256) void transpose_W_kernel(const float* __restrict__ W) {
    __shared__ float tile[64][33];
    const int tid = threadIdx.x;
    const int v0  = blockIdx.x * 32;

    #pragma unroll
    for (int i = 0; i < 2; ++i) {
        int j  = tid + i * 256;
        int e  = j >> 3;
        int vq = (j & 7) * 4;
        float4 val = *reinterpret_cast<const float4*>(W + (size_t)e * VOCAB + v0 + vq);
        tile[e][vq + 0] = val.x;
        tile[e][vq + 1] = val.y;
        tile[e][vq + 2] = val.z;
        tile[e][vq + 3] = val.w;
    }
    __syncthreads();

    {
        int v  = tid >> 3;
        int e8 = (tid & 7) * 8;
        __half2 h[4];
        #pragma unroll
        for (int i = 0; i < 4; ++i) {
            h[i] = __floats2half2_rn(tile[e8 + 2 * i][v], tile[e8 + 2 * i + 1][v]);
        }
        *reinterpret_cast<uint4*>(g_WTh + (size_t)(v0 + v) * EMBED + e8) =
            *reinterpret_cast<uint4*>(h);
    }
}

// ---------------------------------------------------------------------------
// Kernel 2: embedding-bag gather (R9 shape + L1-bypass loads).
// 8 lanes per position, each lane one LDG.128 (8 halves) per id -> 8 lanes
// x 16B = full 128B row. 32 positions per 256-thread block. fp32 accum.
// ---------------------------------------------------------------------------
__global__ __launch_bounds__(256) void gather_sum_kernel(
    const int*   __restrict__ ids,    // [NPOS, KIDS]
    const float* __restrict__ bias,   // [EMBED]
    float*       __restrict__ out)    // [NPOS, EMBED]
{
    __shared__ int sids[32 * KIDS];   // 640 ids for this block's 32 positions

    const int tid  = threadIdx.x;
    const int pos0 = blockIdx.x * 32;

    // Coalesced cooperative id load (640 ints = 2560B).
    #pragma unroll
    for (int i = tid; i < 32 * KIDS; i += 256)
        sids[i] = ids[(size_t)pos0 * KIDS + i];
    __syncthreads();

    const int p   = tid >> 3;         // local position 0..31
    const int sub = tid & 7;          // owns embed elems [8*sub, 8*sub+8)
    const int* myids = sids + p * KIDS;
    const __half* wt = g_WTh + (size_t)sub * 8;

    float acc[8];
    #pragma unroll
    for (int i = 0; i < 8; ++i) acc[i] = 0.f;

    #pragma unroll
    for (int k = 0; k < KIDS; ++k) {
        uint4 raw = ldg_na(wt + (size_t)myids[k] * EMBED);
        const __half2* h = reinterpret_cast<const __half2*>(&raw);
        #pragma unroll
        for (int i = 0; i < 4; ++i) {
            float2 f = __half22float2(h[i]);
            acc[2 * i]     += f.x;
            acc[2 * i + 1] += f.y;
        }
    }

    // Bias (fp32, exact) + output write: 8 floats = two float4.
    const float4 b0 = __ldg(reinterpret_cast<const float4*>(bias + sub * 8));
    const float4 b1 = __ldg(reinterpret_cast<const float4*>(bias + sub * 8 + 4));

    float4 r0 = make_float4(acc[0] + b0.x, acc[1] + b0.y, acc[2] + b0.z, acc[3] + b0.w);
    float4 r1 = make_float4(acc[4] + b1.x, acc[5] + b1.y, acc[6] + b1.z, acc[7] + b1.w);

    float* op = out + (size_t)(pos0 + p) * EMBED + sub * 8;
    *reinterpret_cast<float4*>(op)     = r0;
    *reinterpret_cast<float4*>(op + 4) = r1;
}

// ---------------------------------------------------------------------------
// inputs: 0 = content_input int32 [B,S,K], 1 = W f32 [E,V], 2 = b f32 [E]
// output: f32 [B,S,E]
// ---------------------------------------------------------------------------
extern "C" void kernel_launch(void* const* d_in, const int* in_sizes, int n_in,
                              void* d_out, int out_size) {
    const int*   ids  = (const int*)d_in[0];
    const float* W    = (const float*)d_in[1];
    const float* bias = (const float*)d_in[2];
    float*       out  = (float*)d_out;

    transpose_W_kernel<<<VOCAB / 32, 256>>>(W);            // 3125 blocks
    gather_sum_kernel<<<NPOS / 32, 256>>>(ids, bias, out); // 1600 blocks
}